// round 11
// baseline (speedup 1.0000x reference)
#include <cuda_runtime.h>

// Problem constants
#define BB   256
#define TT   2048
#define INP  64
#define HH   32
#define NCLS 5

// Packed 2-wide fp32 FMA (Blackwell FFMA2 via PTX fma.rn.f32x2)
__device__ __forceinline__ unsigned long long fma2(unsigned long long a,
                                                   unsigned long long b,
                                                   unsigned long long c) {
    unsigned long long d;
    asm("fma.rn.f32x2 %0, %1, %2, %3;" : "=l"(d) : "l"(a), "l"(b), "l"(c));
    return d;
}
__device__ __forceinline__ float2 unpack2(unsigned long long v) {
    float2 r;
    asm("mov.b64 {%0, %1}, %2;" : "=f"(r.x), "=f"(r.y) : "l"(v));
    return r;
}

// One CTA per batch row. 4 warps: warp g computes gate g (i,f,g,o), lane j = hidden unit j.
// Each lane keeps its 160 weights (W_ih row [128] ++ W_hh row [32]) in registers as 80 f32x2.
__global__ void __launch_bounds__(128, 1) ar_decoder_kernel(
    const float* __restrict__ x,    // [B, T, 64]
    const float* __restrict__ Wih,  // [128, 128]
    const float* __restrict__ Whh,  // [128, 32]
    const float* __restrict__ bih,  // [128]
    const float* __restrict__ bhh,  // [128]
    const float* __restrict__ Wfc,  // [5, 32]
    const float* __restrict__ bfc,  // [5]
    const float* __restrict__ emb,  // [5, 64]
    float* __restrict__ out)        // [B, T, 5]
{
    const int b    = blockIdx.x;
    const int tid  = threadIdx.x;
    const int wid  = tid >> 5;
    const int lane = tid & 31;
    const int r    = tid;            // gate row 0..127 (wid*32 + lane)

    __shared__ __align__(16) float s_v[160];   // [ x_t (64) | prev (64) | h (32) ]
    __shared__ float s_g[128];                  // activated gates
    __shared__ float s_emb[NCLS * INP];

    // ---- Load this lane's weight row into registers (packed pairs) ----
    unsigned long long w2[80];
    {
        const ulonglong2* p = reinterpret_cast<const ulonglong2*>(Wih + r * 128);
        #pragma unroll
        for (int i = 0; i < 32; i++) {
            ulonglong2 u = p[i];
            w2[2 * i]     = u.x;
            w2[2 * i + 1] = u.y;
        }
        const ulonglong2* q = reinterpret_cast<const ulonglong2*>(Whh + r * 32);
        #pragma unroll
        for (int i = 0; i < 8; i++) {
            ulonglong2 u = q[i];
            w2[64 + 2 * i]     = u.x;
            w2[64 + 2 * i + 1] = u.y;
        }
    }
    const float brow = bih[r] + bhh[r];

    // ---- Warp-0 persistent state: cell state + classifier weights ----
    float c = 0.0f;
    float wfc0 = 0.f, wfc1 = 0.f, wfc2 = 0.f, wfc3 = 0.f, wfc4 = 0.f;
    float bf0 = 0.f, bf1 = 0.f, bf2 = 0.f, bf3 = 0.f, bf4 = 0.f;
    if (wid == 0) {
        wfc0 = Wfc[0 * HH + lane];
        wfc1 = Wfc[1 * HH + lane];
        wfc2 = Wfc[2 * HH + lane];
        wfc3 = Wfc[3 * HH + lane];
        wfc4 = Wfc[4 * HH + lane];
        bf0 = bfc[0]; bf1 = bfc[1]; bf2 = bfc[2]; bf3 = bfc[3]; bf4 = bfc[4];
    }

    // ---- Init shared state ----
    for (int i = tid; i < NCLS * INP; i += 128) s_emb[i] = emb[i];

    const float4* x4 = reinterpret_cast<const float4*>(x) + (size_t)b * TT * 16;
    if (tid >= 64) s_v[tid] = 0.0f;              // prev = 0
    if (tid < 32)  s_v[128 + tid] = 0.0f;        // h = 0
    if (tid < 16)  reinterpret_cast<float4*>(s_v)[tid] = x4[tid];  // x_0
    __syncthreads();

    float* outp = out + (size_t)b * TT * NCLS;
    float4 xpre = make_float4(0.f, 0.f, 0.f, 0.f);

    for (int t = 0; t < TT; t++) {
        // Prefetch next timestep's input early (hides DRAM latency behind gate compute)
        if (tid < 16 && (t + 1) < TT)
            xpre = x4[(size_t)(t + 1) * 16 + tid];

        // ---- Gates: 160-long dot per lane, packed f32x2, 4 accumulators ----
        const ulonglong2* v2 = reinterpret_cast<const ulonglong2*>(s_v);
        unsigned long long a0 = 0ull, a1 = 0ull, a2 = 0ull, a3 = 0ull; // bit pattern of (+0,+0)
        #pragma unroll
        for (int m = 0; m < 40; m++) {
            ulonglong2 u = v2[m];   // broadcast LDS.128
            if (m & 1) {
                a2 = fma2(w2[2 * m],     u.x, a2);
                a3 = fma2(w2[2 * m + 1], u.y, a3);
            } else {
                a0 = fma2(w2[2 * m],     u.x, a0);
                a1 = fma2(w2[2 * m + 1], u.y, a1);
            }
        }
        float2 f0 = unpack2(a0), f1 = unpack2(a1), f2 = unpack2(a2), f3 = unpack2(a3);
        float acc = brow + ((f0.x + f0.y) + (f1.x + f1.y))
                         + ((f2.x + f2.y) + (f3.x + f3.y));

        // Activation: warps 0,1,3 -> sigmoid (i,f,o); warp 2 -> tanh (g)
        float act;
        if (wid == 2) act = tanhf(acc);
        else          act = 1.0f / (1.0f + expf(-acc));
        s_g[r] = act;
        __syncthreads();

        // ---- Serial tail on warp 0 ----
        if (wid == 0) {
            float i_ = s_g[lane];
            float f_ = s_g[32 + lane];
            float g_ = s_g[64 + lane];
            float o_ = s_g[96 + lane];
            c = f_ * c + i_ * g_;
            float h = o_ * tanhf(c);
            s_v[128 + lane] = h;

            // logits_n = sum_j Wfc[n][j] * h_j  (butterfly reduce, 5 values in parallel)
            float p0 = wfc0 * h, p1 = wfc1 * h, p2 = wfc2 * h, p3 = wfc3 * h, p4 = wfc4 * h;
            #pragma unroll
            for (int off = 16; off > 0; off >>= 1) {
                p0 += __shfl_xor_sync(0xffffffffu, p0, off);
                p1 += __shfl_xor_sync(0xffffffffu, p1, off);
                p2 += __shfl_xor_sync(0xffffffffu, p2, off);
                p3 += __shfl_xor_sync(0xffffffffu, p3, off);
                p4 += __shfl_xor_sync(0xffffffffu, p4, off);
            }
            p0 += bf0; p1 += bf1; p2 += bf2; p3 += bf3; p4 += bf4;

            // argmax (first-max tie-break, matching jnp.argmax)
            int   amax = 0;
            float best = p0;
            if (p1 > best) { best = p1; amax = 1; }
            if (p2 > best) { best = p2; amax = 2; }
            if (p3 > best) { best = p3; amax = 3; }
            if (p4 > best) { best = p4; amax = 4; }

            // log-softmax (fast intrinsics fine here: output-only, argmax unaffected)
            float e0 = __expf(p0 - best);
            float e1 = __expf(p1 - best);
            float e2 = __expf(p2 - best);
            float e3 = __expf(p3 - best);
            float e4 = __expf(p4 - best);
            float lse = best + __logf(e0 + e1 + e2 + e3 + e4);

            if (lane < NCLS) {
                float l = (lane == 0) ? p0 : (lane == 1) ? p1 : (lane == 2) ? p2
                        : (lane == 3) ? p3 : p4;
                outp[(size_t)t * NCLS + lane] = l - lse;
            }

            // prev = emb[amax]
            s_v[64 + lane] = s_emb[amax * INP + lane];
            s_v[96 + lane] = s_emb[amax * INP + 32 + lane];

            // install prefetched x_{t+1}
            if (lane < 16) reinterpret_cast<float4*>(s_v)[lane] = xpre;
        }
        __syncthreads();
    }
}

extern "C" void kernel_launch(void* const* d_in, const int* in_sizes, int n_in,
                              void* d_out, int out_size) {
    // metadata order: x, x_lengths, edge_list, W_ih, W_hh, b_ih, b_hh, W_fc, b_fc, emb
    const float* x   = (const float*)d_in[0];
    // d_in[1] (x_lengths, int64) and d_in[2] (edge_list, int64) are unused by the reference path
    const float* Wih = (const float*)d_in[3];
    const float* Whh = (const float*)d_in[4];
    const float* bih = (const float*)d_in[5];
    const float* bhh = (const float*)d_in[6];
    const float* Wfc = (const float*)d_in[7];
    const float* bfc = (const float*)d_in[8];
    const float* emb = (const float*)d_in[9];
    float* out = (float*)d_out;

    ar_decoder_kernel<<<BB, 128>>>(x, Wih, Whh, bih, bhh, Wfc, bfc, emb, out);
}

// round 12
// speedup vs baseline: 1.0005x; 1.0005x over previous
#include <cuda_runtime.h>

// Problem constants
#define BB   256
#define TT   2048
#define INP  64
#define HH   32
#define NCLS 5

// Packed 2-wide fp32 FMA (Blackwell FFMA2 via PTX fma.rn.f32x2)
__device__ __forceinline__ unsigned long long fma2(unsigned long long a,
                                                   unsigned long long b,
                                                   unsigned long long c) {
    unsigned long long d;
    asm("fma.rn.f32x2 %0, %1, %2, %3;" : "=l"(d) : "l"(a), "l"(b), "l"(c));
    return d;
}
__device__ __forceinline__ float2 unpack2(unsigned long long v) {
    float2 r;
    asm("mov.b64 {%0, %1}, %2;" : "=f"(r.x), "=f"(r.y) : "l"(v));
    return r;
}

// One CTA per batch row. 4 warps: warp g computes gate g (i,f,g,o), lane j = hidden unit j.
// Each lane keeps its 160 weights (W_ih row [128] ++ W_hh row [32]) in registers as 80 f32x2.
__global__ void __launch_bounds__(128, 1) ar_decoder_kernel(
    const float* __restrict__ x,    // [B, T, 64]
    const float* __restrict__ Wih,  // [128, 128]
    const float* __restrict__ Whh,  // [128, 32]
    const float* __restrict__ bih,  // [128]
    const float* __restrict__ bhh,  // [128]
    const float* __restrict__ Wfc,  // [5, 32]
    const float* __restrict__ bfc,  // [5]
    const float* __restrict__ emb,  // [5, 64]
    float* __restrict__ out)        // [B, T, 5]
{
    const int b    = blockIdx.x;
    const int tid  = threadIdx.x;
    const int wid  = tid >> 5;
    const int lane = tid & 31;
    const int r    = tid;            // gate row 0..127 (wid*32 + lane)

    __shared__ __align__(16) float s_v[160];   // [ x_t (64) | prev (64) | h (32) ]
    __shared__ float s_g[128];                  // activated gates
    __shared__ float s_emb[NCLS * INP];

    // ---- Load this lane's weight row into registers (packed pairs) ----
    unsigned long long w2[80];
    {
        const ulonglong2* p = reinterpret_cast<const ulonglong2*>(Wih + r * 128);
        #pragma unroll
        for (int i = 0; i < 32; i++) {
            ulonglong2 u = p[i];
            w2[2 * i]     = u.x;
            w2[2 * i + 1] = u.y;
        }
        const ulonglong2* q = reinterpret_cast<const ulonglong2*>(Whh + r * 32);
        #pragma unroll
        for (int i = 0; i < 8; i++) {
            ulonglong2 u = q[i];
            w2[64 + 2 * i]     = u.x;
            w2[64 + 2 * i + 1] = u.y;
        }
    }
    const float brow = bih[r] + bhh[r];

    // ---- Warp-0 persistent state: cell state + classifier weights ----
    float c = 0.0f;
    float wfc0 = 0.f, wfc1 = 0.f, wfc2 = 0.f, wfc3 = 0.f, wfc4 = 0.f;
    float bf0 = 0.f, bf1 = 0.f, bf2 = 0.f, bf3 = 0.f, bf4 = 0.f;
    if (wid == 0) {
        wfc0 = Wfc[0 * HH + lane];
        wfc1 = Wfc[1 * HH + lane];
        wfc2 = Wfc[2 * HH + lane];
        wfc3 = Wfc[3 * HH + lane];
        wfc4 = Wfc[4 * HH + lane];
        bf0 = bfc[0]; bf1 = bfc[1]; bf2 = bfc[2]; bf3 = bfc[3]; bf4 = bfc[4];
    }

    // ---- Init shared state ----
    for (int i = tid; i < NCLS * INP; i += 128) s_emb[i] = emb[i];

    const float4* x4 = reinterpret_cast<const float4*>(x) + (size_t)b * TT * 16;
    if (tid >= 64) s_v[tid] = 0.0f;              // prev = 0
    if (tid < 32)  s_v[128 + tid] = 0.0f;        // h = 0
    if (tid < 16)  reinterpret_cast<float4*>(s_v)[tid] = x4[tid];  // x_0
    __syncthreads();

    float* outp = out + (size_t)b * TT * NCLS;
    float4 xpre = make_float4(0.f, 0.f, 0.f, 0.f);

    for (int t = 0; t < TT; t++) {
        // Prefetch next timestep's input early (hides DRAM latency behind gate compute)
        if (tid < 16 && (t + 1) < TT)
            xpre = x4[(size_t)(t + 1) * 16 + tid];

        // ---- Gates: 160-long dot per lane, packed f32x2, 4 accumulators ----
        const ulonglong2* v2 = reinterpret_cast<const ulonglong2*>(s_v);
        unsigned long long a0 = 0ull, a1 = 0ull, a2 = 0ull, a3 = 0ull; // bit pattern of (+0,+0)
        #pragma unroll
        for (int m = 0; m < 40; m++) {
            ulonglong2 u = v2[m];   // broadcast LDS.128
            if (m & 1) {
                a2 = fma2(w2[2 * m],     u.x, a2);
                a3 = fma2(w2[2 * m + 1], u.y, a3);
            } else {
                a0 = fma2(w2[2 * m],     u.x, a0);
                a1 = fma2(w2[2 * m + 1], u.y, a1);
            }
        }
        float2 f0 = unpack2(a0), f1 = unpack2(a1), f2 = unpack2(a2), f3 = unpack2(a3);
        float acc = brow + ((f0.x + f0.y) + (f1.x + f1.y))
                         + ((f2.x + f2.y) + (f3.x + f3.y));

        // Activation: warps 0,1,3 -> sigmoid (i,f,o); warp 2 -> tanh (g)
        float act;
        if (wid == 2) act = tanhf(acc);
        else          act = 1.0f / (1.0f + expf(-acc));
        s_g[r] = act;
        __syncthreads();

        // ---- Serial tail on warp 0 ----
        if (wid == 0) {
            float i_ = s_g[lane];
            float f_ = s_g[32 + lane];
            float g_ = s_g[64 + lane];
            float o_ = s_g[96 + lane];
            c = f_ * c + i_ * g_;
            float h = o_ * tanhf(c);
            s_v[128 + lane] = h;

            // logits_n = sum_j Wfc[n][j] * h_j  (butterfly reduce, 5 values in parallel)
            float p0 = wfc0 * h, p1 = wfc1 * h, p2 = wfc2 * h, p3 = wfc3 * h, p4 = wfc4 * h;
            #pragma unroll
            for (int off = 16; off > 0; off >>= 1) {
                p0 += __shfl_xor_sync(0xffffffffu, p0, off);
                p1 += __shfl_xor_sync(0xffffffffu, p1, off);
                p2 += __shfl_xor_sync(0xffffffffu, p2, off);
                p3 += __shfl_xor_sync(0xffffffffu, p3, off);
                p4 += __shfl_xor_sync(0xffffffffu, p4, off);
            }
            p0 += bf0; p1 += bf1; p2 += bf2; p3 += bf3; p4 += bf4;

            // argmax (first-max tie-break, matching jnp.argmax)
            int   amax = 0;
            float best = p0;
            if (p1 > best) { best = p1; amax = 1; }
            if (p2 > best) { best = p2; amax = 2; }
            if (p3 > best) { best = p3; amax = 3; }
            if (p4 > best) { best = p4; amax = 4; }

            // log-softmax (fast intrinsics fine here: output-only, argmax unaffected)
            float e0 = __expf(p0 - best);
            float e1 = __expf(p1 - best);
            float e2 = __expf(p2 - best);
            float e3 = __expf(p3 - best);
            float e4 = __expf(p4 - best);
            float lse = best + __logf(e0 + e1 + e2 + e3 + e4);

            if (lane < NCLS) {
                float l = (lane == 0) ? p0 : (lane == 1) ? p1 : (lane == 2) ? p2
                        : (lane == 3) ? p3 : p4;
                outp[(size_t)t * NCLS + lane] = l - lse;
            }

            // prev = emb[amax]
            s_v[64 + lane] = s_emb[amax * INP + lane];
            s_v[96 + lane] = s_emb[amax * INP + 32 + lane];

            // install prefetched x_{t+1}
            if (lane < 16) reinterpret_cast<float4*>(s_v)[lane] = xpre;
        }
        __syncthreads();
    }
}

extern "C" void kernel_launch(void* const* d_in, const int* in_sizes, int n_in,
                              void* d_out, int out_size) {
    // metadata order: x, x_lengths, edge_list, W_ih, W_hh, b_ih, b_hh, W_fc, b_fc, emb
    const float* x   = (const float*)d_in[0];
    // d_in[1] (x_lengths, int64) and d_in[2] (edge_list, int64) are unused by the reference path
    const float* Wih = (const float*)d_in[3];
    const float* Whh = (const float*)d_in[4];
    const float* bih = (const float*)d_in[5];
    const float* bhh = (const float*)d_in[6];
    const float* Wfc = (const float*)d_in[7];
    const float* bfc = (const float*)d_in[8];
    const float* emb = (const float*)d_in[9];
    float* out = (float*)d_out;

    ar_decoder_kernel<<<BB, 128>>>(x, Wih, Whh, bih, bhh, Wfc, bfc, emb, out);
}

// round 13
// speedup vs baseline: 1.1033x; 1.1027x over previous
#include <cuda_runtime.h>

// Problem constants
#define BB   256
#define TT   2048
#define INP  64
#define HH   32
#define NCLS 5

// ---------------- scratch (no dynamic alloc allowed) ----------------
__device__ float d_GX[(size_t)BB * TT * 128];  // precomputed W_ih[:, :64]@x + b_ih + b_hh
__device__ float d_P[128 * NCLS];              // W_ih[:, 64:128] @ emb[n]  (per gate-row, per class)

// Packed 2-wide fp32 FMA (Blackwell FFMA2 via PTX fma.rn.f32x2)
__device__ __forceinline__ unsigned long long fma2(unsigned long long a,
                                                   unsigned long long b,
                                                   unsigned long long c) {
    unsigned long long d;
    asm("fma.rn.f32x2 %0, %1, %2, %3;" : "=l"(d) : "l"(a), "l"(b), "l"(c));
    return d;
}
__device__ __forceinline__ float2 unpack2(unsigned long long v) {
    float2 r;
    asm("mov.b64 {%0, %1}, %2;" : "=f"(r.x), "=f"(r.y) : "l"(v));
    return r;
}
__device__ __forceinline__ float sel5(int a, float f0, float f1, float f2, float f3, float f4) {
    float r = f0;
    r = (a == 1) ? f1 : r;
    r = (a == 2) ? f2 : r;
    r = (a == 3) ? f3 : r;
    r = (a == 4) ? f4 : r;
    return r;
}

// ---------------- prepass 1: P[r][n] = W_ih[r, 64:128] . emb[n] ----------------
__global__ void p_kernel(const float* __restrict__ Wih, const float* __restrict__ emb) {
    int r = threadIdx.x;  // 0..127
    #pragma unroll
    for (int n = 0; n < NCLS; n++) {
        float a = 0.f;
        #pragma unroll
        for (int k = 0; k < INP; k++)
            a += Wih[r * 128 + 64 + k] * emb[n * INP + k];
        d_P[r * NCLS + n] = a;
    }
}

// ---------------- prepass 2: GX = x @ W_ih[:, :64]^T + (b_ih + b_hh) ----------------
#define GX_CHUNK 64
__global__ void __launch_bounds__(128) gx_kernel(
    const float* __restrict__ x, const float* __restrict__ Wih,
    const float* __restrict__ bih, const float* __restrict__ bhh)
{
    const int r = threadIdx.x;  // gate row 0..127
    const size_t base = (size_t)blockIdx.x * GX_CHUNK;  // bt position

    // W_ih row r, columns 0..63 (x part) as 32 packed pairs
    unsigned long long w[32];
    {
        const ulonglong2* p = reinterpret_cast<const ulonglong2*>(Wih + r * 128);
        #pragma unroll
        for (int i = 0; i < 16; i++) {
            ulonglong2 u = p[i];
            w[2 * i] = u.x; w[2 * i + 1] = u.y;
        }
    }
    const float br = bih[r] + bhh[r];

    __shared__ __align__(16) float sx[INP];

    for (int p = 0; p < GX_CHUNK; p++) {
        size_t bt = base + p;
        __syncthreads();
        if (r < 16)
            reinterpret_cast<float4*>(sx)[r] =
                reinterpret_cast<const float4*>(x + bt * INP)[r];
        __syncthreads();

        const ulonglong2* v2 = reinterpret_cast<const ulonglong2*>(sx);
        unsigned long long a0 = 0ull, a1 = 0ull, a2 = 0ull, a3 = 0ull;
        #pragma unroll
        for (int m = 0; m < 16; m++) {
            ulonglong2 u = v2[m];
            if (m & 1) { a2 = fma2(w[2 * m], u.x, a2); a3 = fma2(w[2 * m + 1], u.y, a3); }
            else       { a0 = fma2(w[2 * m], u.x, a0); a1 = fma2(w[2 * m + 1], u.y, a1); }
        }
        float2 f0 = unpack2(a0), f1 = unpack2(a1), f2 = unpack2(a2), f3 = unpack2(a3);
        d_GX[bt * 128 + r] = br + ((f0.x + f0.y) + (f1.x + f1.y))
                                + ((f2.x + f2.y) + (f3.x + f3.y));
    }
}

// ---------------- recurrent kernel: one warp per batch row, no __syncthreads ----------------
// Lane j owns hidden unit j: gate rows j (i), 32+j (f), 64+j (g), 96+j (o).
// c and h live in-lane; h broadcast via per-warp 32-float SMEM + __syncwarp.
__global__ void __launch_bounds__(64, 1) ar_rec_kernel(
    const float* __restrict__ Whh,  // [128, 32]
    const float* __restrict__ Wfc,  // [5, 32]
    const float* __restrict__ bfc,  // [5]
    float* __restrict__ out)        // [B, T, 5]
{
    const int w = threadIdx.x >> 5;
    const int j = threadIdx.x & 31;
    const int b = blockIdx.x * 2 + w;

    __shared__ __align__(16) float s_h[2][32];

    // W_hh rows for the 4 gates of unit j, packed pairs: wh[g][m] covers h[2m],h[2m+1]
    unsigned long long wh[4][16];
    #pragma unroll
    for (int g = 0; g < 4; g++) {
        const ulonglong2* q = reinterpret_cast<const ulonglong2*>(Whh + (g * 32 + j) * HH);
        #pragma unroll
        for (int i = 0; i < 8; i++) {
            ulonglong2 u = q[i];
            wh[g][2 * i] = u.x; wh[g][2 * i + 1] = u.y;
        }
    }
    float wfc_[NCLS], bf[NCLS];
    #pragma unroll
    for (int n = 0; n < NCLS; n++) { wfc_[n] = Wfc[n * HH + j]; bf[n] = bfc[n]; }

    // P columns for this lane's 4 gate rows (kept as named scalars via constant indexing)
    float Pg[4][NCLS];
    #pragma unroll
    for (int g = 0; g < 4; g++)
        #pragma unroll
        for (int n = 0; n < NCLS; n++)
            Pg[g][n] = d_P[(g * 32 + j) * NCLS + n];

    float c = 0.f, h = 0.f;
    s_h[w][j] = 0.f;
    __syncwarp();

    const float* gxp = d_GX + (size_t)b * TT * 128;
    float gx_c[4], gx_n[4];
    #pragma unroll
    for (int g = 0; g < 4; g++) gx_c[g] = __ldg(gxp + g * 32 + j);

    float* op = out + (size_t)b * TT * NCLS;

    for (int t = 0; t < TT; t++) {
        // prefetch GX for t+1 (consumed next iteration -> ~full-step slack)
        const int tn = (t + 1 < TT) ? t + 1 : t;
        #pragma unroll
        for (int g = 0; g < 4; g++)
            gx_n[g] = __ldg(gxp + (size_t)tn * 128 + g * 32 + j);

        // ---- W_hh . h(t-1) : 4 gate dots, packed, weights in registers ----
        const ulonglong2* hv = reinterpret_cast<const ulonglong2*>(s_h[w]);
        unsigned long long a0[4] = {0ull, 0ull, 0ull, 0ull};
        unsigned long long a1[4] = {0ull, 0ull, 0ull, 0ull};
        #pragma unroll
        for (int m = 0; m < 8; m++) {
            ulonglong2 u = hv[m];  // broadcast LDS.128
            #pragma unroll
            for (int g = 0; g < 4; g++) a0[g] = fma2(wh[g][2 * m],     u.x, a0[g]);
            #pragma unroll
            for (int g = 0; g < 4; g++) a1[g] = fma2(wh[g][2 * m + 1], u.y, a1[g]);
        }

        // ---- logits(t-1) butterfly on current h register (overlaps with dot) ----
        float p0 = wfc_[0] * h, p1 = wfc_[1] * h, p2 = wfc_[2] * h,
              p3 = wfc_[3] * h, p4 = wfc_[4] * h;
        #pragma unroll
        for (int off = 16; off > 0; off >>= 1) {
            p0 += __shfl_xor_sync(0xffffffffu, p0, off);
            p1 += __shfl_xor_sync(0xffffffffu, p1, off);
            p2 += __shfl_xor_sync(0xffffffffu, p2, off);
            p3 += __shfl_xor_sync(0xffffffffu, p3, off);
            p4 += __shfl_xor_sync(0xffffffffu, p4, off);
        }
        p0 += bf[0]; p1 += bf[1]; p2 += bf[2]; p3 += bf[3]; p4 += bf[4];

        // argmax (first-max tie-break, matching jnp.argmax)
        int amax = 0; float best = p0;
        if (p1 > best) { best = p1; amax = 1; }
        if (p2 > best) { best = p2; amax = 2; }
        if (p3 > best) { best = p3; amax = 3; }
        if (p4 > best) { best = p4; amax = 4; }

        // output for step t-1 (fast intrinsics: output-only, argmax unaffected)
        if (t > 0) {
            float e0 = __expf(p0 - best), e1 = __expf(p1 - best), e2 = __expf(p2 - best),
                  e3 = __expf(p3 - best), e4 = __expf(p4 - best);
            float lse = best + __logf(e0 + e1 + e2 + e3 + e4);
            if (j < NCLS)
                op[(size_t)(t - 1) * NCLS + j] = sel5(j, p0, p1, p2, p3, p4) - lse;
        }

        // ---- assemble raw gates: gx + P[:,amax(t-1)] + Whh.h ----
        const float pm = (t > 0) ? 1.f : 0.f;  // prev(-1) = 0
        float raw[4];
        #pragma unroll
        for (int g = 0; g < 4; g++) {
            float2 f0 = unpack2(a0[g]), f1 = unpack2(a1[g]);
            float psel = sel5(amax, Pg[g][0], Pg[g][1], Pg[g][2], Pg[g][3], Pg[g][4]);
            raw[g] = gx_c[g] + pm * psel + ((f0.x + f0.y) + (f1.x + f1.y));
        }

        // ---- LSTM update (accurate math in the feedback path) ----
        float iv = 1.f / (1.f + expf(-raw[0]));
        float fv = 1.f / (1.f + expf(-raw[1]));
        float gv = tanhf(raw[2]);
        float ov = 1.f / (1.f + expf(-raw[3]));
        c = fv * c + iv * gv;
        h = ov * tanhf(c);

        __syncwarp();
        s_h[w][j] = h;
        __syncwarp();

        #pragma unroll
        for (int g = 0; g < 4; g++) gx_c[g] = gx_n[g];
    }

    // final logits for t = TT-1
    {
        float p0 = wfc_[0] * h, p1 = wfc_[1] * h, p2 = wfc_[2] * h,
              p3 = wfc_[3] * h, p4 = wfc_[4] * h;
        #pragma unroll
        for (int off = 16; off > 0; off >>= 1) {
            p0 += __shfl_xor_sync(0xffffffffu, p0, off);
            p1 += __shfl_xor_sync(0xffffffffu, p1, off);
            p2 += __shfl_xor_sync(0xffffffffu, p2, off);
            p3 += __shfl_xor_sync(0xffffffffu, p3, off);
            p4 += __shfl_xor_sync(0xffffffffu, p4, off);
        }
        p0 += bf[0]; p1 += bf[1]; p2 += bf[2]; p3 += bf[3]; p4 += bf[4];
        float best = fmaxf(fmaxf(fmaxf(p0, p1), fmaxf(p2, p3)), p4);
        float e0 = __expf(p0 - best), e1 = __expf(p1 - best), e2 = __expf(p2 - best),
              e3 = __expf(p3 - best), e4 = __expf(p4 - best);
        float lse = best + __logf(e0 + e1 + e2 + e3 + e4);
        if (j < NCLS)
            op[(size_t)(TT - 1) * NCLS + j] = sel5(j, p0, p1, p2, p3, p4) - lse;
    }
}

extern "C" void kernel_launch(void* const* d_in, const int* in_sizes, int n_in,
                              void* d_out, int out_size) {
    // metadata order: x, x_lengths, edge_list, W_ih, W_hh, b_ih, b_hh, W_fc, b_fc, emb
    const float* x   = (const float*)d_in[0];
    const float* Wih = (const float*)d_in[3];
    const float* Whh = (const float*)d_in[4];
    const float* bih = (const float*)d_in[5];
    const float* bhh = (const float*)d_in[6];
    const float* Wfc = (const float*)d_in[7];
    const float* bfc = (const float*)d_in[8];
    const float* emb = (const float*)d_in[9];
    float* out = (float*)d_out;

    p_kernel<<<1, 128>>>(Wih, emb);
    gx_kernel<<<(BB * TT) / GX_CHUNK, 128>>>(x, Wih, bih, bhh);
    ar_rec_kernel<<<BB / 2, 64>>>(Whh, Wfc, bfc, out);
}